// round 11
// baseline (speedup 1.0000x reference)
#include <cuda_runtime.h>
#include <cuda_fp16.h>
#include <cstdint>
#include <cstddef>

// Problem dims
#define BB   16
#define NN   128
#define MMx  1024
#define DNx  512
#define DEx  256
#define PPx  512

// ---------------- scratch (static __device__, no allocation) ----------------
__device__ __half d_Xh  [BB*NN*DNx];      // masked node feats fp16 (2048x512)
__device__ float  d_XWp [BB*NN*256];      // [XW|Xp]
__device__ float  d_h   [BB*NN*128];
__device__ __half d_Egh [BB*MMx*DEx];     // gathered edge feats    (16384x256)
__device__ float  d_EgWe[BB*MMx*128];
__device__ float  d_agg [BB*NN*128];
__device__ __half d_EFph[BB*PPx*DEx];     // edge feats at pairs    (8192x256)
__device__ float  d_Qp  [BB*PPx*128];
// transposed + split weights: [N][K] K-major, fp16 hi/lo
__device__ __half d_WtXWhi[256*512], d_WtXWlo[256*512];
__device__ __half d_WtEghi[128*256], d_WtEglo[128*256];
__device__ __half d_WtQhi [128*256], d_WtQlo [128*256];
__device__ __half d_WtW1hi[768*512], d_WtW1lo[768*512];
__device__ float  d_b1cat[768];
__device__ __half d_W2Thi[32*768], d_W2Tlo[32*768];   // [outcol(pad32)][hidden]

// ---------------- asm helpers ------------------------------------------------
__device__ __forceinline__ uint32_t smem_u32(const void* p) {
    uint32_t a;
    asm("{ .reg .u64 t; cvta.to.shared.u64 t, %1; cvt.u32.u64 %0, t; }" : "=r"(a) : "l"(p));
    return a;
}
#define CP16(sa, ga) \
    asm volatile("cp.async.cg.shared.global [%0], [%1], 16;" :: "r"(sa), "l"(ga))
#define CP_COMMIT() asm volatile("cp.async.commit_group;" ::: "memory")
#define CP_WAIT(n)  asm volatile("cp.async.wait_group %0;" :: "n"(n) : "memory")

#define LDSM4(r, a) \
    asm volatile("ldmatrix.sync.aligned.m8n8.x4.shared.b16 {%0,%1,%2,%3}, [%4];" \
        : "=r"((r)[0]), "=r"((r)[1]), "=r"((r)[2]), "=r"((r)[3]) : "r"(a))

#define MMAH(c, a, b0, b1) \
    asm volatile("mma.sync.aligned.m16n8k16.row.col.f32.f16.f16.f32 " \
        "{%0,%1,%2,%3},{%4,%5,%6,%7},{%8,%9},{%0,%1,%2,%3};" \
        : "+f"((c)[0]), "+f"((c)[1]), "+f"((c)[2]), "+f"((c)[3]) \
        : "r"((a)[0]), "r"((a)[1]), "r"((a)[2]), "r"((a)[3]), "r"(b0), "r"(b1))

#define S_AHI 0
#define S_BHI 8192
#define S_BLO 16384
#define STG   24576
#define GEMM_SMEM  (2 * STG)               // 48 KB
#define F_H    0
#define F_W2HI 32768
#define F_W2LO 40960

// swizzled byte offset of 16B chunk c (0..3) in row r (row = 64B)
__device__ __forceinline__ uint32_t swz(int r, int c) {
    return (uint32_t)(r * 64 + ((c ^ ((r >> 1) & 3)) << 4));
}
// swizzle for 256B rows (16 granules of 16B)
__device__ __forceinline__ uint32_t hswz(int r, int c) {
    return (uint32_t)(r * 256 + ((c ^ (r & 7)) << 4));
}
__device__ __forceinline__ uint32_t hpack(__half a, __half b) {
    __half2 t = __halves2half2(a, b);
    return *reinterpret_cast<uint32_t*>(&t);
}

// ---------------- batched fp16 tensor-core GEMM (no fuse) --------------------
// C[M,N] = op(A @ B^T (relu)); A fp16, B = Bhi+Blo fp16 (2-term).
struct Gd {
    const __half *A, *Bhi, *Blo;
    float* C;
    int ldc, K, tilesX, blkEnd, doRelu, pad;
};
struct Gp { Gd d[3]; int n; };

__global__ __launch_bounds__(256, 2) void gemm_batch(Gp gp)
{
    extern __shared__ char smem[];
    const uint32_t sb = smem_u32(smem);

    int bid = blockIdx.x, di = 0;
    while (di < gp.n - 1 && bid >= gp.d[di].blkEnd) di++;
    const Gd g = gp.d[di];
    const int base  = di ? gp.d[di - 1].blkEnd : 0;
    const int local = bid - base;
    const int row0  = (local / g.tilesX) * 128;
    const int col0  = (local % g.tilesX) * 128;
    const int K     = g.K;
    const int nT    = K >> 5;

    const int tid = threadIdx.x, lane = tid & 31, wid = tid >> 5;
    const int wr = wid & 3, wc = wid >> 2;
    const int fr = tid >> 1, fc0 = (tid & 1) * 2;

    const char* gA  = (const char*)g.A   + ((size_t)(row0 + fr) * K) * 2;
    const char* gBh = (const char*)g.Bhi + ((size_t)(col0 + fr) * K) * 2;
    const char* gBl = (const char*)g.Blo + ((size_t)(col0 + fr) * K) * 2;

    float c[2][8][4];
    #pragma unroll
    for (int mt = 0; mt < 2; mt++)
        #pragma unroll
        for (int nt = 0; nt < 8; nt++)
            #pragma unroll
            for (int i = 0; i < 4; i++) c[mt][nt][i] = 0.f;

    const int arow = wr * 32 + (lane & 7) + (lane & 8);
    const int acs  = (lane & 16) ? 1 : 0;
    const int brow0 = wc * 64 + (lane & 7) + ((lane & 16) ? 8 : 0);
    const int bcs   = (lane & 8) ? 1 : 0;

    {   // prologue: tile 0 -> stage 0
        #pragma unroll
        for (int c2 = 0; c2 < 2; c2++) {
            int cc = fc0 + c2;
            uint32_t so = swz(fr, cc);
            size_t go = cc * 16;
            CP16(sb + S_AHI + so, gA  + go);
            CP16(sb + S_BHI + so, gBh + go);
            CP16(sb + S_BLO + so, gBl + go);
        }
        CP_COMMIT();
    }

    for (int t = 0; t < nT; t++) {
        const int st = (t & 1) * STG;
        CP_WAIT(0);
        __syncthreads();                       // tile t visible; stage st^1 readers done
        if (t + 1 < nT) {                      // prefetch t+1 (race-free: after barrier)
            const int sn = ((t + 1) & 1) * STG;
            const size_t kb = (size_t)(t + 1) * 64;
            #pragma unroll
            for (int c2 = 0; c2 < 2; c2++) {
                int cc = fc0 + c2;
                uint32_t so = swz(fr, cc);
                size_t go = kb + cc * 16;
                CP16(sb + sn + S_AHI + so, gA  + go);
                CP16(sb + sn + S_BHI + so, gBh + go);
                CP16(sb + sn + S_BLO + so, gBl + go);
            }
            CP_COMMIT();
        }
        #pragma unroll
        for (int kk = 0; kk < 2; kk++) {
            uint32_t ah[2][4];
            #pragma unroll
            for (int mt = 0; mt < 2; mt++)
                LDSM4(ah[mt], sb + st + S_AHI + swz(arow + mt * 16, (kk << 1) + acs));
            #pragma unroll
            for (int p = 0; p < 4; p++) {
                uint32_t off = swz(brow0 + p * 16, (kk << 1) + bcs);
                uint32_t bh[4], bl[4];
                LDSM4(bh, sb + st + S_BHI + off);
                LDSM4(bl, sb + st + S_BLO + off);
                #pragma unroll
                for (int mt = 0; mt < 2; mt++) {
                    MMAH(c[mt][2 * p],     ah[mt], bh[0], bh[1]);
                    MMAH(c[mt][2 * p],     ah[mt], bl[0], bl[1]);
                    MMAH(c[mt][2 * p + 1], ah[mt], bh[2], bh[3]);
                    MMAH(c[mt][2 * p + 1], ah[mt], bl[2], bl[3]);
                }
            }
        }
    }

    #pragma unroll
    for (int mt = 0; mt < 2; mt++) {
        int r = row0 + wr * 32 + mt * 16 + (lane >> 2);
        #pragma unroll
        for (int nt = 0; nt < 8; nt++) {
            int cc = col0 + wc * 64 + nt * 8 + 2 * (lane & 3);
            float v0 = c[mt][nt][0], v1 = c[mt][nt][1];
            float v2 = c[mt][nt][2], v3 = c[mt][nt][3];
            if (g.doRelu) {
                v0 = fmaxf(v0, 0.f); v1 = fmaxf(v1, 0.f);
                v2 = fmaxf(v2, 0.f); v3 = fmaxf(v3, 0.f);
            }
            *(float2*)&g.C[(size_t)r * g.ldc + cc]       = make_float2(v0, v1);
            *(float2*)&g.C[(size_t)(r + 8) * g.ldc + cc] = make_float2(v2, v3);
        }
    }
}

// ---------------- gemm_heads: CI built in A-path + W1 GEMM + head MMA --------
// A rows = pairs; K-tile c selects segment: [0,4) h  [4,8) agg  [8,12) relu(Xp)
// [12,16) Qp.  B = W1cat hi/lo.  Epilogue: relu(H+b1) @ (W2hi+W2lo) -> atomic out.
__global__ __launch_bounds__(256) void gemm_heads(
    const int* __restrict__ pairs, const int* __restrict__ num_obj,
    const __half* __restrict__ Bhi, const __half* __restrict__ Blo,
    const float* __restrict__ bias,
    const __half* __restrict__ W2hi, const __half* __restrict__ W2lo,
    float* __restrict__ outp)
{
    extern __shared__ char smem[];
    const uint32_t sb = smem_u32(smem);
    const int local = blockIdx.x;
    const int row0 = (local / 6) * 128;
    const int col0 = (local % 6) * 128;
    const int K = 512, nT = 16;

    const int tid = threadIdx.x, lane = tid & 31, wid = tid >> 5;
    const int wr = wid & 3, wc = wid >> 2;
    const int fr = tid >> 1, half = tid & 1, fc0 = half * 2;

    const int b  = row0 >> 9;
    const int gp = row0 + fr;
    const int p0 = pairs[gp * 2], p1 = pairs[gp * 2 + 1];
    const int no = num_obj[b];

    const char* gBh = (const char*)Bhi + ((size_t)(col0 + fr) * K) * 2;
    const char* gBl = (const char*)Blo + ((size_t)(col0 + fr) * K) * 2;

    const float* hB = d_h   + (size_t)b * 128 * 128;
    const float* aB = d_agg + (size_t)b * 128 * 128;
    const float* xB = d_XWp + (size_t)b * 128 * 256;
    const float* qB = d_Qp  + (size_t)gp * 128;

    float4 v0[4], v1[4];
    auto loadA = [&](int cc) {
        int kc = (cc & 3) * 32 + half * 16;
        int mode = cc >> 2;
        if (mode == 0) {
            const float4* r0 = (const float4*)(hB + (size_t)p0 * 128 + kc);
            const float4* r1 = (const float4*)(hB + (size_t)p1 * 128 + kc);
            #pragma unroll
            for (int j = 0; j < 4; j++) { v0[j] = r0[j]; v1[j] = r1[j]; }
        } else if (mode == 1) {
            const float4* r0 = (const float4*)(aB + (size_t)p0 * 128 + kc);
            const float4* r1 = (const float4*)(aB + (size_t)p1 * 128 + kc);
            float4 z = make_float4(0.f, 0.f, 0.f, 0.f);
            #pragma unroll
            for (int j = 0; j < 4; j++) {
                v0[j] = (p0 < no) ? r0[j] : z;
                v1[j] = (p1 < no) ? r1[j] : z;
            }
        } else if (mode == 2) {
            const float4* r0 = (const float4*)(xB + (size_t)p0 * 256 + 128 + kc);
            const float4* r1 = (const float4*)(xB + (size_t)p1 * 256 + 128 + kc);
            #pragma unroll
            for (int j = 0; j < 4; j++) { v0[j] = r0[j]; v1[j] = r1[j]; }
        } else {
            const float4* r0 = (const float4*)(qB + kc);
            #pragma unroll
            for (int j = 0; j < 4; j++) v0[j] = r0[j];
        }
    };
    auto stsA = [&](int cc, int st) {
        int mode = cc >> 2;
        const float* a  = (const float*)v0;
        const float* bb = (const float*)v1;
        uint32_t pk[8];
        #pragma unroll
        for (int j = 0; j < 8; j++) {
            float x0, x1;
            if (mode == 3)      { x0 = a[2*j];                          x1 = a[2*j+1]; }
            else if (mode == 2) { x0 = fmaxf(a[2*j] + bb[2*j], 0.f);    x1 = fmaxf(a[2*j+1] + bb[2*j+1], 0.f); }
            else                { x0 = a[2*j] + bb[2*j];                x1 = a[2*j+1] + bb[2*j+1]; }
            pk[j] = hpack(__float2half(x0), __float2half(x1));
        }
        *(uint4*)(smem + st + S_AHI + swz(fr, fc0))     = make_uint4(pk[0], pk[1], pk[2], pk[3]);
        *(uint4*)(smem + st + S_AHI + swz(fr, fc0 + 1)) = make_uint4(pk[4], pk[5], pk[6], pk[7]);
    };

    float c[2][8][4];
    #pragma unroll
    for (int mt = 0; mt < 2; mt++)
        #pragma unroll
        for (int nt = 0; nt < 8; nt++)
            #pragma unroll
            for (int i = 0; i < 4; i++) c[mt][nt][i] = 0.f;

    const int arow = wr * 32 + (lane & 7) + (lane & 8);
    const int acs  = (lane & 16) ? 1 : 0;
    const int brow0 = wc * 64 + (lane & 7) + ((lane & 16) ? 8 : 0);
    const int bcs   = (lane & 8) ? 1 : 0;

    loadA(0);
    #pragma unroll
    for (int c2 = 0; c2 < 2; c2++) {
        int cc = fc0 + c2;
        uint32_t so = swz(fr, cc);
        CP16(sb + S_BHI + so, gBh + cc * 16);
        CP16(sb + S_BLO + so, gBl + cc * 16);
    }
    CP_COMMIT();

    for (int t = 0; t < nT; t++) {
        const int st = (t & 1) * STG;
        CP_WAIT(0);
        __syncthreads();                       // B(t) visible; stage readers done
        stsA(t, st);
        if (t + 1 < nT) {
            const int sn = ((t + 1) & 1) * STG;
            const size_t kb = (size_t)(t + 1) * 64;
            #pragma unroll
            for (int c2 = 0; c2 < 2; c2++) {
                int cc = fc0 + c2;
                uint32_t so = swz(fr, cc);
                CP16(sb + sn + S_BHI + so, gBh + kb + cc * 16);
                CP16(sb + sn + S_BLO + so, gBl + kb + cc * 16);
            }
            CP_COMMIT();
            loadA(t + 1);                      // LDG next A; lands during MMA(t)
        }
        __syncthreads();                       // STS A(t) visible
        #pragma unroll
        for (int kk = 0; kk < 2; kk++) {
            uint32_t ah[2][4];
            #pragma unroll
            for (int mt = 0; mt < 2; mt++)
                LDSM4(ah[mt], sb + st + S_AHI + swz(arow + mt * 16, (kk << 1) + acs));
            #pragma unroll
            for (int p = 0; p < 4; p++) {
                uint32_t off = swz(brow0 + p * 16, (kk << 1) + bcs);
                uint32_t bh[4], bl[4];
                LDSM4(bh, sb + st + S_BHI + off);
                LDSM4(bl, sb + st + S_BLO + off);
                #pragma unroll
                for (int mt = 0; mt < 2; mt++) {
                    MMAH(c[mt][2 * p],     ah[mt], bh[0], bh[1]);
                    MMAH(c[mt][2 * p],     ah[mt], bl[0], bl[1]);
                    MMAH(c[mt][2 * p + 1], ah[mt], bh[2], bh[3]);
                    MMAH(c[mt][2 * p + 1], ah[mt], bl[2], bl[3]);
                }
            }
        }
    }
    __syncthreads();                           // all MMAs done before smem reuse

    // ---- head epilogue: H fp16 -> smem; W2 slices via cp.async; MMA ----
    #pragma unroll
    for (int mt = 0; mt < 2; mt++) {
        int rl = wr * 32 + mt * 16 + (lane >> 2);
        #pragma unroll
        for (int nt = 0; nt < 8; nt++) {
            int cl = wc * 64 + nt * 8 + 2 * (lane & 3);
            float b0 = bias[col0 + cl], b1 = bias[col0 + cl + 1];
            float v0f = fmaxf(c[mt][nt][0] + b0, 0.f);
            float v1f = fmaxf(c[mt][nt][1] + b1, 0.f);
            float v2f = fmaxf(c[mt][nt][2] + b0, 0.f);
            float v3f = fmaxf(c[mt][nt][3] + b1, 0.f);
            *(uint32_t*)(smem + F_H + hswz(rl,     cl >> 3) + (cl & 7) * 2) =
                hpack(__float2half(v0f), __float2half(v1f));
            *(uint32_t*)(smem + F_H + hswz(rl + 8, cl >> 3) + (cl & 7) * 2) =
                hpack(__float2half(v2f), __float2half(v3f));
        }
    }
    {   // W2 slices: rows j 0..31, k = col0..col0+127
        int j = tid >> 3, c8 = tid & 7;
        #pragma unroll
        for (int hf = 0; hf < 2; hf++) {
            int c16 = c8 + hf * 8;
            size_t so = ((size_t)j * 768 + col0 + c16 * 8) * 2;
            CP16(sb + F_W2HI + hswz(j, c16), (const char*)W2hi + so);
            CP16(sb + F_W2LO + hswz(j, c16), (const char*)W2lo + so);
        }
        CP_COMMIT(); CP_WAIT(0);
    }
    __syncthreads();

    const int head = col0 >> 8;
    const int outd = (head == 0) ? 9 : (head == 1) ? 6 : 17;
    const size_t obase = (head == 0) ? 0 : (head == 1) ? 73728 : 122880;

    const int wm = wid * 16;
    float cN[4][4];
    #pragma unroll
    for (int i = 0; i < 4; i++)
        #pragma unroll
        for (int j = 0; j < 4; j++) cN[i][j] = 0.f;

    const int harow = wm + (lane & 7) + (lane & 8);
    const int hacs  = (lane & 16) ? 1 : 0;
    const int wbr   = (lane & 7) + ((lane & 16) ? 8 : 0);
    const int wbcs  = (lane & 8) ? 1 : 0;

    #pragma unroll
    for (int ks = 0; ks < 8; ks++) {
        uint32_t a[4];
        LDSM4(a, sb + F_H + hswz(harow, 2 * ks + hacs));
        #pragma unroll
        for (int nb = 0; nb < 2; nb++) {
            uint32_t off = hswz(nb * 16 + wbr, 2 * ks + wbcs);
            uint32_t bh[4], bl[4];
            LDSM4(bh, sb + F_W2HI + off);
            LDSM4(bl, sb + F_W2LO + off);
            MMAH(cN[2 * nb],     a, bh[0], bh[1]);
            MMAH(cN[2 * nb],     a, bl[0], bl[1]);
            MMAH(cN[2 * nb + 1], a, bh[2], bh[3]);
            MMAH(cN[2 * nb + 1], a, bl[2], bl[3]);
        }
    }
    #pragma unroll
    for (int ns = 0; ns < 4; ns++) {
        int col = ns * 8 + 2 * (lane & 3);
        int r0 = row0 + wm + (lane >> 2);
        if (col < outd) {
            atomicAdd(&outp[obase + (size_t)r0 * outd + col],       cN[ns][0]);
            atomicAdd(&outp[obase + (size_t)(r0 + 8) * outd + col], cN[ns][2]);
        }
        if (col + 1 < outd) {
            atomicAdd(&outp[obase + (size_t)r0 * outd + col + 1],       cN[ns][1]);
            atomicAdd(&outp[obase + (size_t)(r0 + 8) * outd + col + 1], cN[ns][3]);
        }
    }
}

// ---------------- fp16 helpers ----------------------------------------------
__device__ __forceinline__ void hsplit(float x, __half& hi, __half& lo) {
    hi = __float2half(x);
    lo = __float2half(x - __half2float(hi));
}
__device__ __forceinline__ uint2 h4(float4 v) {
    uint2 r;
    r.x = hpack(__float2half(v.x), __float2half(v.y));
    r.y = hpack(__float2half(v.z), __float2half(v.w));
    return r;
}

// ---------------- setup_all: weight packing + input prep ---------------------
// grid (256 thr): [0,1152) pack | [1152,2176) maskX+aggzero | [2176,6272) Eg
//                 [6272,8320) EFp | [8320,8576) out bias init
__global__ void setup_all(const float* __restrict__ nf, const float* __restrict__ ef,
                          const int* __restrict__ ei, const int* __restrict__ pairs,
                          const int* __restrict__ num_obj, const int* __restrict__ num_edges,
                          const float* __restrict__ Wn,  const float* __restrict__ Wn2,
                          const float* __restrict__ We,  const float* __restrict__ We2,
                          const float* __restrict__ lrW1,  const float* __restrict__ lrb1,
                          const float* __restrict__ scrW1, const float* __restrict__ scrb1,
                          const float* __restrict__ mrW1,  const float* __restrict__ mrb1,
                          const float* __restrict__ lrW2,  const float* __restrict__ crW2,
                          const float* __restrict__ mrW2,
                          const float* __restrict__ lrb2,  const float* __restrict__ crb2,
                          const float* __restrict__ mrb2,  float* __restrict__ out)
{
    int blk = blockIdx.x, t = threadIdx.x;
    if (blk < 1152) {
        if (blk < 256) {
            int n = blk;
            #pragma unroll
            for (int j = 0; j < 2; j++) {
                int k = t + j * 256;
                float v = (n < 128) ? Wn[k * 128 + n] : Wn2[k * 128 + (n - 128)];
                __half hi, lo; hsplit(v, hi, lo);
                d_WtXWhi[n * 512 + k] = hi; d_WtXWlo[n * 512 + k] = lo;
            }
        } else if (blk < 384) {
            int n = blk - 256, k = t;
            __half hi, lo;
            hsplit(We [k * 128 + n], hi, lo);
            d_WtEghi[n * 256 + k] = hi; d_WtEglo[n * 256 + k] = lo;
            hsplit(We2[k * 128 + n], hi, lo);
            d_WtQhi [n * 256 + k] = hi; d_WtQlo [n * 256 + k] = lo;
        } else {
            int n = blk - 384;
            const float* W; const float* bb; const float* W2; int cn, outd;
            if (n < 256)      { W = lrW1;  bb = lrb1;  W2 = lrW2; cn = n;       outd = 9;  }
            else if (n < 512) { W = scrW1; bb = scrb1; W2 = crW2; cn = n - 256; outd = 6;  }
            else              { W = mrW1;  bb = mrb1;  W2 = mrW2; cn = n - 512; outd = 17; }
            #pragma unroll
            for (int j = 0; j < 2; j++) {
                int k = t + j * 256;
                __half hi, lo; hsplit(W[k * 256 + cn], hi, lo);
                d_WtW1hi[n * 512 + k] = hi; d_WtW1lo[n * 512 + k] = lo;
            }
            if (t == 0) d_b1cat[n] = bb[cn];
            if (t < 32) {
                float v = (t < outd) ? W2[cn * outd + t] : 0.f;
                __half hi, lo; hsplit(v, hi, lo);
                d_W2Thi[t * 768 + n] = hi; d_W2Tlo[t * 768 + n] = lo;
            }
        }
    } else if (blk < 2176) {
        int idx = (blk - 1152) * 2 + (t >> 7);       // 0..2047
        int b = idx >> 7, n = idx & 127, tt = t & 127;
        float4 v = make_float4(0.f, 0.f, 0.f, 0.f);
        if (n < num_obj[b]) v = ((const float4*)nf)[(size_t)idx * 128 + tt];
        ((uint2*)d_Xh)[(size_t)idx * 128 + tt] = h4(v);
        d_agg[(size_t)idx * 128 + tt] = 0.f;
    } else if (blk < 6272) {
        int idx = (blk - 2176) * 4 + (t >> 6);       // 0..16383
        int b = idx >> 10, m = idx & 1023, tt = t & 63;
        float4 v = make_float4(0.f, 0.f, 0.f, 0.f);
        if (m < num_edges[b]) {
            int s = ei[b * 2048 + m];
            int d = ei[b * 2048 + 1024 + m];
            v = ((const float4*)ef)[(((size_t)b * 128 + s) * 128 + d) * 64 + tt];
        }
        ((uint2*)d_Egh)[(size_t)idx * 64 + tt] = h4(v);
    } else if (blk < 8320) {
        int idx = (blk - 6272) * 4 + (t >> 6);       // 0..8191
        int b = idx / 512, tt = t & 63;
        int p0 = pairs[idx * 2], p1 = pairs[idx * 2 + 1];
        float4 v = ((const float4*)ef)[(((size_t)b * 128 + p0) * 128 + p1) * 64 + tt];
        ((uint2*)d_EFph)[(size_t)idx * 64 + tt] = h4(v);
    } else {
        int basei = (blk - 8320) * 1024 + t * 4;     // 262144 total
        #pragma unroll
        for (int j = 0; j < 4; j++) {
            int i = basei + j;
            float v;
            if (i < 73728)       v = lrb2[i % 9];
            else if (i < 122880) v = crb2[(i - 73728) % 6];
            else                 v = mrb2[(i - 122880) % 17];
            out[i] = v;
        }
    }
}

// ---------------- graph_all: adj conv + line conv (+fused src scatter) -------
// grid: [0,2048) adj_h | [2048,18432) line conv.  128 thr.
__global__ void graph_all(const float* __restrict__ adj, const float* __restrict__ ladj,
                          const int* __restrict__ ei,
                          const int* __restrict__ num_obj, const int* __restrict__ num_edges)
{
    __shared__ int   s_jidx[1024];
    __shared__ float s_jw[1024];
    __shared__ int   s_cnt;

    int blk = blockIdx.x, t = threadIdx.x;
    if (blk < 2048) {
        int b = blk >> 7, i = blk & 127;
        int no = num_obj[b];
        float* outp = &d_h[(size_t)blk * 128];
        if (i >= no) { outp[t] = 0.f; return; }
        if (t == 0) s_cnt = 0;
        __syncthreads();
        float w = adj[(size_t)blk * 128 + t];
        if (t < no && w != 0.f) { int p = atomicAdd(&s_cnt, 1); s_jidx[p] = t; s_jw[p] = w; }
        __syncthreads();
        const float* xw = &d_XWp[(size_t)b * 128 * 256];
        float a0 = xw[i * 256 + t], a1 = 0.f, a2 = 0.f, a3 = 0.f;  // eye term
        int c = s_cnt, k = 0;
        for (; k + 3 < c; k += 4) {
            a0 = fmaf(s_jw[k],     xw[s_jidx[k] * 256 + t],     a0);
            a1 = fmaf(s_jw[k + 1], xw[s_jidx[k + 1] * 256 + t], a1);
            a2 = fmaf(s_jw[k + 2], xw[s_jidx[k + 2] * 256 + t], a2);
            a3 = fmaf(s_jw[k + 3], xw[s_jidx[k + 3] * 256 + t], a3);
        }
        for (; k < c; k++) a0 = fmaf(s_jw[k], xw[s_jidx[k] * 256 + t], a0);
        outp[t] = fmaxf((a0 + a1) + (a2 + a3), 0.f);
    } else {
        int lb = blk - 2048;
        int b = lb >> 10, m = lb & 1023;
        int ne = num_edges[b];
        if (m >= ne) return;
        if (t == 0) s_cnt = 0;
        __syncthreads();
        const float4* lp4 = (const float4*)(ladj + (size_t)lb * 1024);
        #pragma unroll
        for (int it = 0; it < 2; it++) {
            int j4 = t + it * 128;
            float4 w4 = lp4[j4];
            int jb = j4 * 4;
            if (w4.x != 0.f && jb     < ne) { int p = atomicAdd(&s_cnt, 1); s_jidx[p] = jb;     s_jw[p] = w4.x; }
            if (w4.y != 0.f && jb + 1 < ne) { int p = atomicAdd(&s_cnt, 1); s_jidx[p] = jb + 1; s_jw[p] = w4.y; }
            if (w4.z != 0.f && jb + 2 < ne) { int p = atomicAdd(&s_cnt, 1); s_jidx[p] = jb + 2; s_jw[p] = w4.z; }
            if (w4.w != 0.f && jb + 3 < ne) { int p = atomicAdd(&s_cnt, 1); s_jidx[p] = jb + 3; s_jw[p] = w4.w; }
        }
        __syncthreads();
        const float* ew = &d_EgWe[(size_t)b * 1024 * 128];
        float a0 = ew[m * 128 + t], a1 = 0.f, a2 = 0.f, a3 = 0.f;  // eye term
        int c = s_cnt, k = 0;
        for (; k + 3 < c; k += 4) {
            a0 = fmaf(s_jw[k],     ew[s_jidx[k] * 128 + t],     a0);
            a1 = fmaf(s_jw[k + 1], ew[s_jidx[k + 1] * 128 + t], a1);
            a2 = fmaf(s_jw[k + 2], ew[s_jidx[k + 2] * 128 + t], a2);
            a3 = fmaf(s_jw[k + 3], ew[s_jidx[k + 3] * 128 + t], a3);
        }
        for (; k < c; k++) a0 = fmaf(s_jw[k], ew[s_jidx[k] * 128 + t], a0);
        float acc = fmaxf((a0 + a1) + (a2 + a3), 0.f);
        if (acc != 0.f) {
            int s = ei[b * 2048 + m];
            atomicAdd(&d_agg[((size_t)b * 128 + s) * 128 + t], acc);
        }
    }
}

// ---------------- launch -----------------------------------------------------
extern "C" void kernel_launch(void* const* d_in, const int* in_sizes, int n_in,
                              void* d_out, int out_size)
{
    const float* nf    = (const float*)d_in[0];
    const float* ef    = (const float*)d_in[1];
    const float* adj   = (const float*)d_in[2];
    const float* ladj  = (const float*)d_in[3];
    const int*   ei    = (const int*)  d_in[4];
    const int*   pairs = (const int*)  d_in[5];
    const int*   nobj  = (const int*)  d_in[6];
    const int*   nedg  = (const int*)  d_in[7];
    const float* Wn    = (const float*)d_in[8];
    const float* We    = (const float*)d_in[9];
    const float* Wn2   = (const float*)d_in[10];
    const float* We2   = (const float*)d_in[11];
    const float* scrW1 = (const float*)d_in[12];
    const float* scrb1 = (const float*)d_in[13];
    const float* scrW2 = (const float*)d_in[14];
    const float* scrb2 = (const float*)d_in[15];
    const float* lrW1  = (const float*)d_in[16];
    const float* lrb1  = (const float*)d_in[17];
    const float* lrW2  = (const float*)d_in[18];
    const float* lrb2  = (const float*)d_in[19];
    const float* mrW1  = (const float*)d_in[20];
    const float* mrb1  = (const float*)d_in[21];
    const float* mrW2  = (const float*)d_in[22];
    const float* mrb2  = (const float*)d_in[23];
    float* out = (float*)d_out;

    cudaFuncSetAttribute(gemm_batch, cudaFuncAttributeMaxDynamicSharedMemorySize, GEMM_SMEM);
    cudaFuncSetAttribute(gemm_heads, cudaFuncAttributeMaxDynamicSharedMemorySize, GEMM_SMEM);

    __half *pXh, *pEgh, *pEFph;
    __half *pWtXWhi, *pWtXWlo, *pWtEghi, *pWtEglo, *pWtQhi, *pWtQlo, *pWtW1hi, *pWtW1lo;
    __half *pW2hi, *pW2lo;
    float *pXWp, *pEgWe, *pQp, *pb1;
    cudaGetSymbolAddress((void**)&pXh,     d_Xh);
    cudaGetSymbolAddress((void**)&pEgh,    d_Egh);
    cudaGetSymbolAddress((void**)&pEFph,   d_EFph);
    cudaGetSymbolAddress((void**)&pWtXWhi, d_WtXWhi);
    cudaGetSymbolAddress((void**)&pWtXWlo, d_WtXWlo);
    cudaGetSymbolAddress((void**)&pWtEghi, d_WtEghi);
    cudaGetSymbolAddress((void**)&pWtEglo, d_WtEglo);
    cudaGetSymbolAddress((void**)&pWtQhi,  d_WtQhi);
    cudaGetSymbolAddress((void**)&pWtQlo,  d_WtQlo);
    cudaGetSymbolAddress((void**)&pWtW1hi, d_WtW1hi);
    cudaGetSymbolAddress((void**)&pWtW1lo, d_WtW1lo);
    cudaGetSymbolAddress((void**)&pW2hi,   d_W2Thi);
    cudaGetSymbolAddress((void**)&pW2lo,   d_W2Tlo);
    cudaGetSymbolAddress((void**)&pXWp,    d_XWp);
    cudaGetSymbolAddress((void**)&pEgWe,   d_EgWe);
    cudaGetSymbolAddress((void**)&pQp,     d_Qp);
    cudaGetSymbolAddress((void**)&pb1,     d_b1cat);

    // 1. weight packing + input prep + agg zero + out bias init
    setup_all<<<8576, 256>>>(nf, ef, ei, pairs, nobj, nedg,
                             Wn, Wn2, We, We2, lrW1, lrb1, scrW1, scrb1,
                             mrW1, mrb1, lrW2, scrW2, mrW2, lrb2, scrb2, mrb2, out);
    // 2. batched GEMM: XWp (32) | EgWe (128) | Qp (64)
    {
        Gp gp;
        gp.n = 3;
        gp.d[0] = { pXh,   pWtXWhi, pWtXWlo, pXWp,  256, 512, 2,  32, 0, 0 };
        gp.d[1] = { pEgh,  pWtEghi, pWtEglo, pEgWe, 128, 256, 1, 160, 0, 0 };
        gp.d[2] = { pEFph, pWtQhi,  pWtQlo,  pQp,   128, 256, 1, 224, 1, 0 };
        gemm_batch<<<224, 256, GEMM_SMEM>>>(gp);
    }
    // 3. adj conv + line conv + fused src scatter
    graph_all<<<18432, 128>>>(adj, ladj, ei, nobj, nedg);
    // 4. CI-in-A-path W1 GEMM + relu + tensor-core heads -> out
    gemm_heads<<<384, 256, GEMM_SMEM>>>(pairs, nobj, pWtW1hi, pWtW1lo,
                                        pb1, pW2hi, pW2lo, out);
}